// round 8
// baseline (speedup 1.0000x reference)
#include <cuda_runtime.h>
#include <cuda_bf16.h>
#include <math.h>
#include <stdint.h>

// Feature gate: tcgen05 is only legal when compiling for an 'a' (or family)
// target. The harness also builds a plain compute_103 PTX pass where these
// instructions must not appear.
#if !defined(__CUDA_ARCH__) || defined(__CUDA_ARCH_FEAT_SM103_ALL) || \
    defined(__CUDA_ARCH_FEAT_SM100_ALL) || defined(__CUDA_ARCH_FEAT_SM101_ALL) || \
    defined(__CUDA_ARCH_FEAT_SM110_ALL) || defined(__CUDA_ARCH_FAMILY_SPECIFIC__)
#define TC_OK 1
#else
#define TC_OK 0
#endif

// ---------------------------------------------------------------------------
// Problem constants
// ---------------------------------------------------------------------------
constexpr int B_     = 2;
constexpr int S_     = 2048;
constexpr int HID_   = 2048;
constexpr int NH_    = 16;
constexpr int NKV_   = 8;
constexpr int HD_    = 128;
constexpr int GATE_  = NH_;                       // 16
constexpr int KV_DIM_ = NKV_ * HD_;               // 1024
constexpr int QKV_OUT_ = NH_ * HD_ + GATE_ + 2 * KV_DIM_;  // 4112
constexpr int QKV_PAD_ = 4224;                    // 33 * 128 (padded N for GEMM)
constexpr int MROWS_ = B_ * S_;                   // 4096
constexpr int ADIM_  = NH_ * HD_;                 // 2048

// qkv row layout: [0,2048) q | [2048,2064) gate | [2064,3088) k | [3088,4112) v
constexpr int OFF_GATE_ = HID_;                   // 2048
constexpr int OFF_K_    = HID_ + GATE_;           // 2064
constexpr int OFF_V_    = HID_ + GATE_ + KV_DIM_; // 3088

// ---------------------------------------------------------------------------
// Scratch (device globals; no allocation allowed)
// ---------------------------------------------------------------------------
__device__ __align__(16) float g_qkv[(size_t)MROWS_ * QKV_PAD_];          // 69 MB
__device__ __align__(16) __nv_bfloat16 g_h_hi[(size_t)MROWS_ * HID_];
__device__ __align__(16) __nv_bfloat16 g_h_lo[(size_t)MROWS_ * HID_];
__device__ __align__(16) __nv_bfloat16 g_wq_hi[(size_t)QKV_PAD_ * HID_];
__device__ __align__(16) __nv_bfloat16 g_wq_lo[(size_t)QKV_PAD_ * HID_];
__device__ __align__(16) __nv_bfloat16 g_wo_hi[(size_t)HID_ * ADIM_];
__device__ __align__(16) __nv_bfloat16 g_wo_lo[(size_t)HID_ * ADIM_];
__device__ __align__(16) __nv_bfloat16 g_at_hi[(size_t)MROWS_ * ADIM_];
__device__ __align__(16) __nv_bfloat16 g_at_lo[(size_t)MROWS_ * ADIM_];

// ---------------------------------------------------------------------------
// fp32 -> (bf16 hi, bf16 lo) split kernels
// ---------------------------------------------------------------------------
__device__ __forceinline__ void split4_store(
    const float4 v, __nv_bfloat16* hi, __nv_bfloat16* lo, size_t e)
{
    float x[4] = {v.x, v.y, v.z, v.w};
    __nv_bfloat16 h[4], l[4];
#pragma unroll
    for (int i = 0; i < 4; i++) {
        h[i] = __float2bfloat16_rn(x[i]);
        l[i] = __float2bfloat16_rn(x[i] - __bfloat162float(h[i]));
    }
    __nv_bfloat162 h0; h0.x = h[0]; h0.y = h[1];
    __nv_bfloat162 h1; h1.x = h[2]; h1.y = h[3];
    __nv_bfloat162 l0; l0.x = l[0]; l0.y = l[1];
    __nv_bfloat162 l1; l1.x = l[2]; l1.y = l[3];
    *(__nv_bfloat162*)(hi + e)     = h0;
    *(__nv_bfloat162*)(hi + e + 2) = h1;
    *(__nv_bfloat162*)(lo + e)     = l0;
    *(__nv_bfloat162*)(lo + e + 2) = l1;
}

__global__ void __launch_bounds__(256)
split_hidden_kernel(const float* __restrict__ src)
{
    const size_t total = (size_t)MROWS_ * HID_ / 4;
    for (size_t idx = (size_t)blockIdx.x * blockDim.x + threadIdx.x;
         idx < total; idx += (size_t)gridDim.x * blockDim.x) {
        const size_t e = idx * 4;
        split4_store(*(const float4*)(src + e), g_h_hi, g_h_lo, e);
    }
}

__global__ void __launch_bounds__(256)
split_wq_kernel(const float* __restrict__ src)   // pad rows 4112..4223 with 0
{
    const size_t total = (size_t)QKV_PAD_ * HID_ / 4;
    for (size_t idx = (size_t)blockIdx.x * blockDim.x + threadIdx.x;
         idx < total; idx += (size_t)gridDim.x * blockDim.x) {
        const size_t e = idx * 4;
        const size_t row = e / HID_;
        float4 v = (row < (size_t)QKV_OUT_) ? *(const float4*)(src + e)
                                            : make_float4(0.f, 0.f, 0.f, 0.f);
        split4_store(v, g_wq_hi, g_wq_lo, e);
    }
}

__global__ void __launch_bounds__(256)
split_wo_kernel(const float* __restrict__ src)
{
    const size_t total = (size_t)HID_ * ADIM_ / 4;
    for (size_t idx = (size_t)blockIdx.x * blockDim.x + threadIdx.x;
         idx < total; idx += (size_t)gridDim.x * blockDim.x) {
        const size_t e = idx * 4;
        split4_store(*(const float4*)(src + e), g_wo_hi, g_wo_lo, e);
    }
}

// ---------------------------------------------------------------------------
// GEMM (NT): C[M,N] = A[M,K] @ B[N,K]^T with split-bf16 ~fp32 accuracy.
// tcgen05 path when the arch feature is available, FFMA fallback otherwise.
// N is padded to a multiple of 128 (operand arrays zero-padded), no guards.
// ---------------------------------------------------------------------------
#define SWZ(o) ((o) ^ (((o) >> 3) & 0x70))

__device__ __forceinline__ uint32_t smem_u32(const void* p) {
    uint32_t a;
    asm("{ .reg .u64 t; cvta.to.shared.u64 t, %1; cvt.u32.u64 %0, t; }"
        : "=r"(a) : "l"(p));
    return a;
}

constexpr int TILE_BYTES_  = 128 * 128;               // 16 KB per bf16 tile
constexpr int STAGE_BYTES_ = 4 * TILE_BYTES_;         // Ahi, Alo, Bhi, Blo
constexpr int GEMM_SMEM_   = 1024 + 2 * STAGE_BYTES_ + 64;

#if TC_OK
// K-major SW128 descriptor base: layout=SW128, version=1, SBO=64, LBO=1
constexpr uint64_t DESC_BASE_ =
    (2ull << 61) | (1ull << 46) | (64ull << 32) | (1ull << 16);

__device__ __forceinline__ uint64_t mk_desc(uint32_t addr) {
    return DESC_BASE_ | ((uint64_t)(addr >> 4) & 0x3FFF);
}

// idesc: dtype=F32, atype=BF16, btype=BF16, N=128, M=128 (K-major both)
constexpr uint32_t IDESC_ =
    (1u << 4) | (1u << 7) | (1u << 10) | ((128u / 8) << 17) | ((128u / 16) << 24);

__device__ __forceinline__ void mma_bf16_ss(
    uint32_t d_tmem, uint64_t a_desc, uint64_t b_desc, uint32_t en)
{
    asm volatile(
        "{\n\t"
        ".reg .pred p;\n\t"
        "setp.ne.u32 p, %4, 0;\n\t"
        "tcgen05.mma.cta_group::1.kind::f16 [%0], %1, %2, %3, {%5, %5, %5, %5}, p;\n\t"
        "}"
        :: "r"(d_tmem), "l"(a_desc), "l"(b_desc), "r"(IDESC_), "r"(en), "r"(0u)
        : "memory");
}
#endif

__device__ __forceinline__ void mbar_init(uint32_t a, uint32_t cnt) {
    asm volatile("mbarrier.init.shared.b64 [%0], %1;" :: "r"(a), "r"(cnt) : "memory");
}
__device__ __forceinline__ void mbar_wait(uint32_t a, uint32_t parity) {
    asm volatile(
        "{\n\t"
        ".reg .pred P;\n\t"
        "WL%=:\n\t"
        "mbarrier.try_wait.parity.acquire.cta.shared::cta.b64 P, [%0], %1, 0x989680;\n\t"
        "@!P bra WL%=;\n\t"
        "}"
        :: "r"(a), "r"(parity) : "memory");
}

__device__ __forceinline__ void load_tile_bf16(
    const __nv_bfloat16* __restrict__ g, int row0, int kbase, int K,
    char* tile, int t)
{
#pragma unroll
    for (int j = 0; j < 4; j++) {
        const int u = t + 256 * j;          // 0..1023
        const int row = u >> 3;             // 0..127
        const int c   = u & 7;              // 16B column
        uint4 v = *(const uint4*)(g + (size_t)(row0 + row) * K + kbase + c * 8);
        *(uint4*)(tile + SWZ(row * 128 + c * 16)) = v;
    }
}

#if TC_OK
__device__ __forceinline__ void gemm_body(
    const __nv_bfloat16* __restrict__ a_hi, const __nv_bfloat16* __restrict__ a_lo,
    const __nv_bfloat16* __restrict__ b_hi, const __nv_bfloat16* __restrict__ b_lo,
    float* __restrict__ C, int K, int ldc)
{
    extern __shared__ char smem_raw[];
    const uint32_t sraw = smem_u32(smem_raw);
    const uint32_t abase = (sraw + 1023u) & ~1023u;          // 1KB-align tiles
    char* smem = smem_raw + (abase - sraw);

    const int t  = threadIdx.x;
    const int wid = t >> 5, lid = t & 31;
    const int m0 = blockIdx.y * 128;
    const int n0 = blockIdx.x * 128;

    const uint32_t ctrl = abase + 2 * STAGE_BYTES_;   // tmem ptr @+0, mbars @+16,+24
    if (wid == 0) {
        asm volatile("tcgen05.alloc.cta_group::1.sync.aligned.shared::cta.b32 [%0], %1;"
                     :: "r"(ctrl), "r"(128u) : "memory");
    }
    if (t == 0) { mbar_init(ctrl + 16, 1); mbar_init(ctrl + 24, 1); }
    __syncthreads();
    uint32_t tmem;
    asm volatile("ld.shared.b32 %0, [%1];" : "=r"(tmem) : "r"(ctrl));

    const int nchunk = K / 64;

    // prologue: chunk 0 -> stage 0
    load_tile_bf16(a_hi, m0, 0, K, smem + 0 * TILE_BYTES_, t);
    load_tile_bf16(a_lo, m0, 0, K, smem + 1 * TILE_BYTES_, t);
    load_tile_bf16(b_hi, n0, 0, K, smem + 2 * TILE_BYTES_, t);
    load_tile_bf16(b_lo, n0, 0, K, smem + 3 * TILE_BYTES_, t);
    asm volatile("fence.proxy.async.shared::cta;" ::: "memory");
    __syncthreads();

    for (int i = 0; i < nchunk; i++) {
        const int st = i & 1;
        if (t == 0) {
            const uint32_t so = abase + st * STAGE_BYTES_;
            const uint64_t dAh = mk_desc(so + 0 * TILE_BYTES_);
            const uint64_t dAl = mk_desc(so + 1 * TILE_BYTES_);
            const uint64_t dBh = mk_desc(so + 2 * TILE_BYTES_);
            const uint64_t dBl = mk_desc(so + 3 * TILE_BYTES_);
#pragma unroll
            for (int ks = 0; ks < 4; ks++) {
                const uint32_t en0 = (i > 0 || ks > 0) ? 1u : 0u;
                mma_bf16_ss(tmem, dAh + ks * 2, dBh + ks * 2, en0);
                mma_bf16_ss(tmem, dAh + ks * 2, dBl + ks * 2, 1u);
                mma_bf16_ss(tmem, dAl + ks * 2, dBh + ks * 2, 1u);
            }
            asm volatile(
                "tcgen05.commit.cta_group::1.mbarrier::arrive::one.shared::cluster.b64 [%0];"
                :: "r"(ctrl + 16 + (uint32_t)st * 8) : "memory");
        }
        if (i + 1 < nchunk) {
            if (i >= 1)   // buf (i+1)&1 was used by chunk i-1; wait for its MMAs
                mbar_wait(ctrl + 16 + (uint32_t)((i - 1) & 1) * 8,
                          (uint32_t)(((i - 1) >> 1) & 1));
            char* dst = smem + ((i + 1) & 1) * STAGE_BYTES_;
            const int kb = (i + 1) * 64;
            load_tile_bf16(a_hi, m0, kb, K, dst + 0 * TILE_BYTES_, t);
            load_tile_bf16(a_lo, m0, kb, K, dst + 1 * TILE_BYTES_, t);
            load_tile_bf16(b_hi, n0, kb, K, dst + 2 * TILE_BYTES_, t);
            load_tile_bf16(b_lo, n0, kb, K, dst + 3 * TILE_BYTES_, t);
            asm volatile("fence.proxy.async.shared::cta;" ::: "memory");
        }
        __syncthreads();
    }

    mbar_wait(ctrl + 16 + (uint32_t)((nchunk - 1) & 1) * 8,
              (uint32_t)(((nchunk - 1) >> 1) & 1));
    asm volatile("tcgen05.fence::after_thread_sync;" ::: "memory");

    // Epilogue: warp w -> rows (w&3)*32 + lane, column half (w>>2)*64
    const int mrow = m0 + (wid & 3) * 32 + lid;
    const int cb   = (wid >> 2) * 64;
#pragma unroll
    for (int half = 0; half < 2; half++) {
        uint32_t r[32];
        const uint32_t taddr = tmem + (uint32_t)(cb + half * 32);
        asm volatile(
            "tcgen05.ld.sync.aligned.32x32b.x32.b32 "
            "{%0, %1, %2, %3, %4, %5, %6, %7, "
            " %8, %9, %10, %11, %12, %13, %14, %15, "
            " %16, %17, %18, %19, %20, %21, %22, %23, "
            " %24, %25, %26, %27, %28, %29, %30, %31}, [%32];"
            : "=r"(r[0]),  "=r"(r[1]),  "=r"(r[2]),  "=r"(r[3]),
              "=r"(r[4]),  "=r"(r[5]),  "=r"(r[6]),  "=r"(r[7]),
              "=r"(r[8]),  "=r"(r[9]),  "=r"(r[10]), "=r"(r[11]),
              "=r"(r[12]), "=r"(r[13]), "=r"(r[14]), "=r"(r[15]),
              "=r"(r[16]), "=r"(r[17]), "=r"(r[18]), "=r"(r[19]),
              "=r"(r[20]), "=r"(r[21]), "=r"(r[22]), "=r"(r[23]),
              "=r"(r[24]), "=r"(r[25]), "=r"(r[26]), "=r"(r[27]),
              "=r"(r[28]), "=r"(r[29]), "=r"(r[30]), "=r"(r[31])
            : "r"(taddr));
        asm volatile("tcgen05.wait::ld.sync.aligned;" ::: "memory");
        float* cp = C + (size_t)mrow * ldc + n0 + cb + half * 32;
#pragma unroll
        for (int j = 0; j < 32; j += 4) {
            float4 v = make_float4(__uint_as_float(r[j]),     __uint_as_float(r[j + 1]),
                                   __uint_as_float(r[j + 2]), __uint_as_float(r[j + 3]));
            *(float4*)(cp + j) = v;
        }
    }

    __syncthreads();
    if (wid == 0) {
        asm volatile("tcgen05.relinquish_alloc_permit.cta_group::1.sync.aligned;" ::: "memory");
        asm volatile("tcgen05.dealloc.cta_group::1.sync.aligned.b32 %0, %1;"
                     :: "r"(tmem), "r"(128u));
    }
}

#else  // ------------------- FFMA fallback (non-'a' PTX pass) ----------------

__device__ __forceinline__ void ld4_split(
    const __nv_bfloat16* __restrict__ hi, const __nv_bfloat16* __restrict__ lo,
    size_t off, float* o)
{
    __nv_bfloat162 h0 = *(const __nv_bfloat162*)(hi + off);
    __nv_bfloat162 h1 = *(const __nv_bfloat162*)(hi + off + 2);
    __nv_bfloat162 l0 = *(const __nv_bfloat162*)(lo + off);
    __nv_bfloat162 l1 = *(const __nv_bfloat162*)(lo + off + 2);
    o[0] = __bfloat162float(h0.x) + __bfloat162float(l0.x);
    o[1] = __bfloat162float(h0.y) + __bfloat162float(l0.y);
    o[2] = __bfloat162float(h1.x) + __bfloat162float(l1.x);
    o[3] = __bfloat162float(h1.y) + __bfloat162float(l1.y);
}

__device__ __forceinline__ void gemm_body(
    const __nv_bfloat16* __restrict__ a_hi, const __nv_bfloat16* __restrict__ a_lo,
    const __nv_bfloat16* __restrict__ b_hi, const __nv_bfloat16* __restrict__ b_lo,
    float* __restrict__ C, int K, int ldc)
{
    __shared__ float As[8][132];
    __shared__ float Bs[8][132];

    const int t  = threadIdx.x;
    const int m0 = blockIdx.y * 128;
    const int n0 = blockIdx.x * 128;
    const int ty = t >> 4;
    const int tx = t & 15;
    const int lrow = t >> 1;
    const int lcol = (t & 1) << 2;

    float acc[8][8];
#pragma unroll
    for (int i = 0; i < 8; i++)
#pragma unroll
        for (int j = 0; j < 8; j++) acc[i][j] = 0.f;

    const size_t aoff = (size_t)(m0 + lrow) * K + lcol;
    const size_t boff = (size_t)(n0 + lrow) * K + lcol;

    float av[4], bv[4];
    ld4_split(a_hi, a_lo, aoff, av);
    ld4_split(b_hi, b_lo, boff, bv);

    for (int k0 = 0; k0 < K; k0 += 8) {
#pragma unroll
        for (int q = 0; q < 4; q++) {
            As[lcol + q][lrow] = av[q];
            Bs[lcol + q][lrow] = bv[q];
        }
        __syncthreads();

        if (k0 + 8 < K) {
            ld4_split(a_hi, a_lo, aoff + k0 + 8, av);
            ld4_split(b_hi, b_lo, boff + k0 + 8, bv);
        }

#pragma unroll
        for (int k = 0; k < 8; k++) {
            float ra[8], rb[8];
            *(float4*)&ra[0] = *(const float4*)&As[k][ty * 8];
            *(float4*)&ra[4] = *(const float4*)&As[k][ty * 8 + 4];
            *(float4*)&rb[0] = *(const float4*)&Bs[k][tx * 8];
            *(float4*)&rb[4] = *(const float4*)&Bs[k][tx * 8 + 4];
#pragma unroll
            for (int i = 0; i < 8; i++)
#pragma unroll
                for (int j = 0; j < 8; j++)
                    acc[i][j] = fmaf(ra[i], rb[j], acc[i][j]);
        }
        __syncthreads();
    }

#pragma unroll
    for (int i = 0; i < 8; i++) {
        const int m = m0 + ty * 8 + i;
#pragma unroll
        for (int j = 0; j < 8; j += 4) {
            const int n = n0 + tx * 8 + j;
            float4 v = make_float4(acc[i][j], acc[i][j + 1],
                                   acc[i][j + 2], acc[i][j + 3]);
            *(float4*)(C + (size_t)m * ldc + n) = v;
        }
    }
}
#endif  // TC_OK

__global__ void __launch_bounds__(256)
gemm_qkv_tc_kernel()
{
    gemm_body(g_h_hi, g_h_lo, g_wq_hi, g_wq_lo, g_qkv, HID_, QKV_PAD_);
}

__global__ void __launch_bounds__(256)
gemm_o_tc_kernel(float* __restrict__ out)
{
    gemm_body(g_at_hi, g_at_lo, g_wo_hi, g_wo_lo, out, ADIM_, HID_);
}

// ---------------------------------------------------------------------------
// RoPE in place on g_qkv: q heads (16) and k heads (8), 64 pairs each
// ---------------------------------------------------------------------------
__global__ void __launch_bounds__(256)
rope_kernel(const float* __restrict__ cosp, const float* __restrict__ sinp)
{
    const int row = blockIdx.x;            // 0..4095 (= b*S + s)
    const int s   = row & (S_ - 1);
    float* rp = g_qkv + (size_t)row * QKV_PAD_;

    for (int idx = threadIdx.x; idx < (NH_ + NKV_) * (HD_ / 2); idx += 256) {
        const int head = idx >> 6;          // 0..23
        const int d    = idx & 63;          // 0..63
        const int off  = (head < NH_) ? head * HD_
                                      : OFF_K_ + (head - NH_) * HD_;
        const float x1 = rp[off + d];
        const float x2 = rp[off + d + 64];
        const float c1 = cosp[s * HD_ + d];
        const float c2 = cosp[s * HD_ + d + 64];
        const float s1 = sinp[s * HD_ + d];
        const float s2 = sinp[s * HD_ + d + 64];
        rp[off + d]      = x1 * c1 - x2 * s1;
        rp[off + d + 64] = x2 * c2 + x1 * s2;
    }
}

// ---------------------------------------------------------------------------
// Flash-style attention, fp32; epilogue emits bf16 hi/lo for the O projection
// ---------------------------------------------------------------------------
constexpr int ATTN_SMEM_ = (128 * 65 + 128 * 65 + 64 * 128 + 64 * 65) * 4; // 115968

__global__ void __launch_bounds__(256)
attn_kernel()
{
    extern __shared__ float sm[];
    float* Qs = sm;                 // 128*65
    float* Ks = Qs + 128 * 65;      // 128*65
    float* Vs = Ks + 128 * 65;      // 64*128
    float* Ps = Vs + 64 * 128;      // 64*65

    const int qt = blockIdx.x;      // 0..31
    const int h  = blockIdx.y;      // 0..15
    const int b  = blockIdx.z;      // 0..1
    const int kh = h >> 1;          // GQA: rep = 2
    const int t  = threadIdx.x;
    const int ty = t >> 4;
    const int tx = t & 15;
    const int q0 = qt * 64;

    const float* qbase = g_qkv + (size_t)b * S_ * QKV_PAD_;

    {
        const float sc = 0.08838834764831845f;   // 1/sqrt(128)
#pragma unroll
        for (int it = 0; it < 8; it++) {
            const int lin = t + 256 * it;
            const int r   = lin >> 5;
            const int d0  = (lin & 31) << 2;
            const float4 v = *(const float4*)(
                qbase + (size_t)(q0 + r) * QKV_PAD_ + h * HD_ + d0);
            Qs[(d0 + 0) * 65 + r] = v.x * sc;
            Qs[(d0 + 1) * 65 + r] = v.y * sc;
            Qs[(d0 + 2) * 65 + r] = v.z * sc;
            Qs[(d0 + 3) * 65 + r] = v.w * sc;
        }
    }

    float m_i[4], l_i[4], acc[4][8];
#pragma unroll
    for (int i = 0; i < 4; i++) {
        m_i[i] = -1e30f;
        l_i[i] = 0.f;
#pragma unroll
        for (int j = 0; j < 8; j++) acc[i][j] = 0.f;
    }
    __syncthreads();

    const int koff = OFF_K_ + kh * HD_;
    const int voff = OFF_V_ + kh * HD_;

    for (int kt = 0; kt < S_ / 64; kt++) {
        const int k0 = kt * 64;

#pragma unroll
        for (int it = 0; it < 8; it++) {
            const int lin = t + 256 * it;
            const int r   = lin >> 5;
            const int d0  = (lin & 31) << 2;
            const float* rowp = qbase + (size_t)(k0 + r) * QKV_PAD_;
            const float4 kv = *(const float4*)(rowp + koff + d0);
            Ks[(d0 + 0) * 65 + r] = kv.x;
            Ks[(d0 + 1) * 65 + r] = kv.y;
            Ks[(d0 + 2) * 65 + r] = kv.z;
            Ks[(d0 + 3) * 65 + r] = kv.w;
            *(float4*)(Vs + r * 128 + d0) = *(const float4*)(rowp + voff + d0);
        }
        __syncthreads();

        float s4[4][4];
#pragma unroll
        for (int i = 0; i < 4; i++)
#pragma unroll
            for (int j = 0; j < 4; j++) s4[i][j] = 0.f;

#pragma unroll 8
        for (int k = 0; k < 128; k++) {
            float a0 = Qs[k * 65 + ty * 4 + 0];
            float a1 = Qs[k * 65 + ty * 4 + 1];
            float a2 = Qs[k * 65 + ty * 4 + 2];
            float a3 = Qs[k * 65 + ty * 4 + 3];
            float b0 = Ks[k * 65 + tx * 4 + 0];
            float b1 = Ks[k * 65 + tx * 4 + 1];
            float b2 = Ks[k * 65 + tx * 4 + 2];
            float b3 = Ks[k * 65 + tx * 4 + 3];
            s4[0][0] = fmaf(a0, b0, s4[0][0]); s4[0][1] = fmaf(a0, b1, s4[0][1]);
            s4[0][2] = fmaf(a0, b2, s4[0][2]); s4[0][3] = fmaf(a0, b3, s4[0][3]);
            s4[1][0] = fmaf(a1, b0, s4[1][0]); s4[1][1] = fmaf(a1, b1, s4[1][1]);
            s4[1][2] = fmaf(a1, b2, s4[1][2]); s4[1][3] = fmaf(a1, b3, s4[1][3]);
            s4[2][0] = fmaf(a2, b0, s4[2][0]); s4[2][1] = fmaf(a2, b1, s4[2][1]);
            s4[2][2] = fmaf(a2, b2, s4[2][2]); s4[2][3] = fmaf(a2, b3, s4[2][3]);
            s4[3][0] = fmaf(a3, b0, s4[3][0]); s4[3][1] = fmaf(a3, b1, s4[3][1]);
            s4[3][2] = fmaf(a3, b2, s4[3][2]); s4[3][3] = fmaf(a3, b3, s4[3][3]);
        }

#pragma unroll
        for (int i = 0; i < 4; i++) {
            float rm = fmaxf(fmaxf(s4[i][0], s4[i][1]), fmaxf(s4[i][2], s4[i][3]));
#pragma unroll
            for (int o = 1; o < 16; o <<= 1)
                rm = fmaxf(rm, __shfl_xor_sync(0xffffffffu, rm, o));
            const float mn = fmaxf(m_i[i], rm);
            const float al = __expf(m_i[i] - mn);
            m_i[i] = mn;
            float rs = 0.f;
#pragma unroll
            for (int j = 0; j < 4; j++) {
                const float p = __expf(s4[i][j] - mn);
                rs += p;
                Ps[(tx * 4 + j) * 65 + ty * 4 + i] = p;
            }
#pragma unroll
            for (int o = 1; o < 16; o <<= 1)
                rs += __shfl_xor_sync(0xffffffffu, rs, o);
            l_i[i] = l_i[i] * al + rs;
#pragma unroll
            for (int j = 0; j < 8; j++) acc[i][j] *= al;
        }
        __syncthreads();

#pragma unroll 4
        for (int c = 0; c < 64; c++) {
            const float a0 = Ps[c * 65 + ty * 4 + 0];
            const float a1 = Ps[c * 65 + ty * 4 + 1];
            const float a2 = Ps[c * 65 + ty * 4 + 2];
            const float a3 = Ps[c * 65 + ty * 4 + 3];
            float rb[8];
            *(float4*)&rb[0] = *(const float4*)(Vs + c * 128 + tx * 8);
            *(float4*)&rb[4] = *(const float4*)(Vs + c * 128 + tx * 8 + 4);
#pragma unroll
            for (int j = 0; j < 8; j++) {
                acc[0][j] = fmaf(a0, rb[j], acc[0][j]);
                acc[1][j] = fmaf(a1, rb[j], acc[1][j]);
                acc[2][j] = fmaf(a2, rb[j], acc[2][j]);
                acc[3][j] = fmaf(a3, rb[j], acc[3][j]);
            }
        }
        __syncthreads();
    }

    // Epilogue: gate * O/l, then split to bf16 hi/lo for the O-projection
#pragma unroll
    for (int i = 0; i < 4; i++) {
        const int r = q0 + ty * 4 + i;
        const float gl = qbase[(size_t)r * QKV_PAD_ + OFF_GATE_ + h];
        const float gate = 1.f / (1.f + __expf(-gl));
        const float w = gate / l_i[i];
        const size_t e = (size_t)(b * S_ + r) * ADIM_ + h * HD_ + tx * 8;
        float o[8];
#pragma unroll
        for (int j = 0; j < 8; j++) o[j] = acc[i][j] * w;
#pragma unroll
        for (int j = 0; j < 8; j += 2) {
            __nv_bfloat16 h0 = __float2bfloat16_rn(o[j]);
            __nv_bfloat16 h1 = __float2bfloat16_rn(o[j + 1]);
            __nv_bfloat16 l0 = __float2bfloat16_rn(o[j]     - __bfloat162float(h0));
            __nv_bfloat16 l1 = __float2bfloat16_rn(o[j + 1] - __bfloat162float(h1));
            __nv_bfloat162 hp; hp.x = h0; hp.y = h1;
            __nv_bfloat162 lp; lp.x = l0; lp.y = l1;
            *(__nv_bfloat162*)(g_at_hi + e + j) = hp;
            *(__nv_bfloat162*)(g_at_lo + e + j) = lp;
        }
    }
}

// ---------------------------------------------------------------------------
// Launch
// ---------------------------------------------------------------------------
extern "C" void kernel_launch(void* const* d_in, const int* in_sizes, int n_in,
                              void* d_out, int out_size)
{
    (void)in_sizes; (void)n_in; (void)out_size;
    const float* hidden = (const float*)d_in[0];   // [B,S,HID]
    const float* cosp   = (const float*)d_in[1];   // [S,HD]
    const float* sinp   = (const float*)d_in[2];   // [S,HD]
    const float* w_qkv  = (const float*)d_in[3];   // [QKV_OUT,HID]
    const float* w_o    = (const float*)d_in[4];   // [HID, NH*HD]
    float* out = (float*)d_out;                    // [B,S,HID]

    cudaFuncSetAttribute(gemm_qkv_tc_kernel,
                         cudaFuncAttributeMaxDynamicSharedMemorySize, GEMM_SMEM_);
    cudaFuncSetAttribute(gemm_o_tc_kernel,
                         cudaFuncAttributeMaxDynamicSharedMemorySize, GEMM_SMEM_);
    cudaFuncSetAttribute(attn_kernel,
                         cudaFuncAttributeMaxDynamicSharedMemorySize, ATTN_SMEM_);

    // 0) split fp32 -> bf16 hi/lo (weights + activations)
    split_hidden_kernel<<<8192, 256>>>(hidden);
    split_wq_kernel<<<8448, 256>>>(w_qkv);
    split_wo_kernel<<<4096, 256>>>(w_o);

    // 1) QKV projection: g_qkv = hidden @ w_qkv^T
    gemm_qkv_tc_kernel<<<dim3(QKV_PAD_ / 128, MROWS_ / 128), 256, GEMM_SMEM_>>>();

    // 2) RoPE in place on q and k
    rope_kernel<<<MROWS_, 256>>>(cosp, sinp);

    // 3) Attention + gate -> g_at_hi/lo (bf16 split)
    attn_kernel<<<dim3(S_ / 64, NH_, B_), 256, ATTN_SMEM_>>>();

    // 4) Output projection: out = attn @ w_o^T
    gemm_o_tc_kernel<<<dim3(HID_ / 128, MROWS_ / 128), 256, GEMM_SMEM_>>>(out);
}

// round 9
// speedup vs baseline: 1.0043x; 1.0043x over previous
#include <cuda_runtime.h>
#include <cuda_bf16.h>
#include <math.h>
#include <stdint.h>

// Feature gate: tcgen05 is only legal when compiling for an 'a' (or family)
// target. The harness also builds a plain compute_103 PTX pass where these
// instructions must not appear.
#if !defined(__CUDA_ARCH__) || defined(__CUDA_ARCH_FEAT_SM103_ALL) || \
    defined(__CUDA_ARCH_FEAT_SM100_ALL) || defined(__CUDA_ARCH_FEAT_SM101_ALL) || \
    defined(__CUDA_ARCH_FEAT_SM110_ALL) || defined(__CUDA_ARCH_FAMILY_SPECIFIC__)
#define TC_OK 1
#else
#define TC_OK 0
#endif

// ---------------------------------------------------------------------------
// Problem constants
// ---------------------------------------------------------------------------
constexpr int B_     = 2;
constexpr int S_     = 2048;
constexpr int HID_   = 2048;
constexpr int NH_    = 16;
constexpr int NKV_   = 8;
constexpr int HD_    = 128;
constexpr int GATE_  = NH_;                       // 16
constexpr int KV_DIM_ = NKV_ * HD_;               // 1024
constexpr int QKV_OUT_ = NH_ * HD_ + GATE_ + 2 * KV_DIM_;  // 4112
constexpr int QKV_PAD_ = 4224;                    // 33 * 128 (padded N for GEMM)
constexpr int MROWS_ = B_ * S_;                   // 4096
constexpr int ADIM_  = NH_ * HD_;                 // 2048

// qkv row layout: [0,2048) q | [2048,2064) gate | [2064,3088) k | [3088,4112) v
constexpr int OFF_GATE_ = HID_;                   // 2048
constexpr int OFF_K_    = HID_ + GATE_;           // 2064
constexpr int OFF_V_    = HID_ + GATE_ + KV_DIM_; // 3088

// ---------------------------------------------------------------------------
// Scratch (device globals; no allocation allowed)
// ---------------------------------------------------------------------------
__device__ __align__(16) float g_qkv[(size_t)MROWS_ * QKV_PAD_];          // 69 MB
__device__ __align__(16) __nv_bfloat16 g_h_hi[(size_t)MROWS_ * HID_];
__device__ __align__(16) __nv_bfloat16 g_h_lo[(size_t)MROWS_ * HID_];
__device__ __align__(16) __nv_bfloat16 g_wq_hi[(size_t)QKV_PAD_ * HID_];
__device__ __align__(16) __nv_bfloat16 g_wq_lo[(size_t)QKV_PAD_ * HID_];
__device__ __align__(16) __nv_bfloat16 g_wo_hi[(size_t)HID_ * ADIM_];
__device__ __align__(16) __nv_bfloat16 g_wo_lo[(size_t)HID_ * ADIM_];
__device__ __align__(16) __nv_bfloat16 g_at_hi[(size_t)MROWS_ * ADIM_];
__device__ __align__(16) __nv_bfloat16 g_at_lo[(size_t)MROWS_ * ADIM_];

// ---------------------------------------------------------------------------
// fp32 -> (bf16 hi, bf16 lo) split kernels
// ---------------------------------------------------------------------------
__device__ __forceinline__ void split4_store(
    const float4 v, __nv_bfloat16* hi, __nv_bfloat16* lo, size_t e)
{
    float x[4] = {v.x, v.y, v.z, v.w};
    __nv_bfloat16 h[4], l[4];
#pragma unroll
    for (int i = 0; i < 4; i++) {
        h[i] = __float2bfloat16_rn(x[i]);
        l[i] = __float2bfloat16_rn(x[i] - __bfloat162float(h[i]));
    }
    __nv_bfloat162 h0; h0.x = h[0]; h0.y = h[1];
    __nv_bfloat162 h1; h1.x = h[2]; h1.y = h[3];
    __nv_bfloat162 l0; l0.x = l[0]; l0.y = l[1];
    __nv_bfloat162 l1; l1.x = l[2]; l1.y = l[3];
    *(__nv_bfloat162*)(hi + e)     = h0;
    *(__nv_bfloat162*)(hi + e + 2) = h1;
    *(__nv_bfloat162*)(lo + e)     = l0;
    *(__nv_bfloat162*)(lo + e + 2) = l1;
}

__global__ void __launch_bounds__(256)
split_hidden_kernel(const float* __restrict__ src)
{
    const size_t total = (size_t)MROWS_ * HID_ / 4;
    for (size_t idx = (size_t)blockIdx.x * blockDim.x + threadIdx.x;
         idx < total; idx += (size_t)gridDim.x * blockDim.x) {
        const size_t e = idx * 4;
        split4_store(*(const float4*)(src + e), g_h_hi, g_h_lo, e);
    }
}

__global__ void __launch_bounds__(256)
split_wq_kernel(const float* __restrict__ src)   // pad rows 4112..4223 with 0
{
    const size_t total = (size_t)QKV_PAD_ * HID_ / 4;
    for (size_t idx = (size_t)blockIdx.x * blockDim.x + threadIdx.x;
         idx < total; idx += (size_t)gridDim.x * blockDim.x) {
        const size_t e = idx * 4;
        const size_t row = e / HID_;
        float4 v = (row < (size_t)QKV_OUT_) ? *(const float4*)(src + e)
                                            : make_float4(0.f, 0.f, 0.f, 0.f);
        split4_store(v, g_wq_hi, g_wq_lo, e);
    }
}

__global__ void __launch_bounds__(256)
split_wo_kernel(const float* __restrict__ src)
{
    const size_t total = (size_t)HID_ * ADIM_ / 4;
    for (size_t idx = (size_t)blockIdx.x * blockDim.x + threadIdx.x;
         idx < total; idx += (size_t)gridDim.x * blockDim.x) {
        const size_t e = idx * 4;
        split4_store(*(const float4*)(src + e), g_wo_hi, g_wo_lo, e);
    }
}

// ---------------------------------------------------------------------------
// GEMM (NT): C[M,N] = A[M,K] @ B[N,K]^T with split-bf16 ~fp32 accuracy.
// tcgen05 path when the arch feature is available, FFMA fallback otherwise.
// N is padded to a multiple of 128 (operand arrays zero-padded), no guards.
// ---------------------------------------------------------------------------
#define SWZ(o) ((o) ^ (((o) >> 3) & 0x70))

__device__ __forceinline__ uint32_t smem_u32(const void* p) {
    uint32_t a;
    asm("{ .reg .u64 t; cvta.to.shared.u64 t, %1; cvt.u32.u64 %0, t; }"
        : "=r"(a) : "l"(p));
    return a;
}

constexpr int TILE_BYTES_  = 128 * 128;               // 16 KB per bf16 tile
constexpr int STAGE_BYTES_ = 4 * TILE_BYTES_;         // Ahi, Alo, Bhi, Blo
constexpr int GEMM_SMEM_   = 1024 + 2 * STAGE_BYTES_ + 64;

#if TC_OK
// K-major SW128 descriptor base: layout=SW128, version=1, SBO=64, LBO=1
constexpr uint64_t DESC_BASE_ =
    (2ull << 61) | (1ull << 46) | (64ull << 32) | (1ull << 16);

__device__ __forceinline__ uint64_t mk_desc(uint32_t addr) {
    return DESC_BASE_ | ((uint64_t)(addr >> 4) & 0x3FFF);
}

// idesc: dtype=F32, atype=BF16, btype=BF16, N=128, M=128 (K-major both)
constexpr uint32_t IDESC_ =
    (1u << 4) | (1u << 7) | (1u << 10) | ((128u / 8) << 17) | ((128u / 16) << 24);

__device__ __forceinline__ void mma_bf16_ss(
    uint32_t d_tmem, uint64_t a_desc, uint64_t b_desc, uint32_t en)
{
    asm volatile(
        "{\n\t"
        ".reg .pred p;\n\t"
        "setp.ne.u32 p, %4, 0;\n\t"
        "tcgen05.mma.cta_group::1.kind::f16 [%0], %1, %2, %3, {%5, %5, %5, %5}, p;\n\t"
        "}"
        :: "r"(d_tmem), "l"(a_desc), "l"(b_desc), "r"(IDESC_), "r"(en), "r"(0u)
        : "memory");
}
#endif

__device__ __forceinline__ void mbar_init(uint32_t a, uint32_t cnt) {
    asm volatile("mbarrier.init.shared.b64 [%0], %1;" :: "r"(a), "r"(cnt) : "memory");
}
__device__ __forceinline__ void mbar_wait(uint32_t a, uint32_t parity) {
    asm volatile(
        "{\n\t"
        ".reg .pred P;\n\t"
        "WL%=:\n\t"
        "mbarrier.try_wait.parity.acquire.cta.shared::cta.b64 P, [%0], %1, 0x989680;\n\t"
        "@!P bra WL%=;\n\t"
        "}"
        :: "r"(a), "r"(parity) : "memory");
}

__device__ __forceinline__ void load_tile_bf16(
    const __nv_bfloat16* __restrict__ g, int row0, int kbase, int K,
    char* tile, int t)
{
#pragma unroll
    for (int j = 0; j < 4; j++) {
        const int u = t + 256 * j;          // 0..1023
        const int row = u >> 3;             // 0..127
        const int c   = u & 7;              // 16B column
        uint4 v = *(const uint4*)(g + (size_t)(row0 + row) * K + kbase + c * 8);
        *(uint4*)(tile + SWZ(row * 128 + c * 16)) = v;
    }
}

#if TC_OK
__device__ __forceinline__ void gemm_body(
    const __nv_bfloat16* __restrict__ a_hi, const __nv_bfloat16* __restrict__ a_lo,
    const __nv_bfloat16* __restrict__ b_hi, const __nv_bfloat16* __restrict__ b_lo,
    float* __restrict__ C, int K, int ldc)
{
    extern __shared__ char smem_raw[];
    const uint32_t sraw = smem_u32(smem_raw);
    const uint32_t abase = (sraw + 1023u) & ~1023u;          // 1KB-align tiles
    char* smem = smem_raw + (abase - sraw);

    const int t  = threadIdx.x;
    const int wid = t >> 5, lid = t & 31;
    const int m0 = blockIdx.y * 128;
    const int n0 = blockIdx.x * 128;

    const uint32_t ctrl = abase + 2 * STAGE_BYTES_;   // tmem ptr @+0, mbars @+16,+24
    if (wid == 0) {
        asm volatile("tcgen05.alloc.cta_group::1.sync.aligned.shared::cta.b32 [%0], %1;"
                     :: "r"(ctrl), "r"(128u) : "memory");
    }
    if (t == 0) { mbar_init(ctrl + 16, 1); mbar_init(ctrl + 24, 1); }
    __syncthreads();
    uint32_t tmem;
    asm volatile("ld.shared.b32 %0, [%1];" : "=r"(tmem) : "r"(ctrl));

    const int nchunk = K / 64;

    // prologue: chunk 0 -> stage 0
    load_tile_bf16(a_hi, m0, 0, K, smem + 0 * TILE_BYTES_, t);
    load_tile_bf16(a_lo, m0, 0, K, smem + 1 * TILE_BYTES_, t);
    load_tile_bf16(b_hi, n0, 0, K, smem + 2 * TILE_BYTES_, t);
    load_tile_bf16(b_lo, n0, 0, K, smem + 3 * TILE_BYTES_, t);
    asm volatile("fence.proxy.async.shared::cta;" ::: "memory");
    __syncthreads();

    for (int i = 0; i < nchunk; i++) {
        const int st = i & 1;
        if (t == 0) {
            const uint32_t so = abase + st * STAGE_BYTES_;
            const uint64_t dAh = mk_desc(so + 0 * TILE_BYTES_);
            const uint64_t dAl = mk_desc(so + 1 * TILE_BYTES_);
            const uint64_t dBh = mk_desc(so + 2 * TILE_BYTES_);
            const uint64_t dBl = mk_desc(so + 3 * TILE_BYTES_);
#pragma unroll
            for (int ks = 0; ks < 4; ks++) {
                const uint32_t en0 = (i > 0 || ks > 0) ? 1u : 0u;
                mma_bf16_ss(tmem, dAh + ks * 2, dBh + ks * 2, en0);
                mma_bf16_ss(tmem, dAh + ks * 2, dBl + ks * 2, 1u);
                mma_bf16_ss(tmem, dAl + ks * 2, dBh + ks * 2, 1u);
            }
            asm volatile(
                "tcgen05.commit.cta_group::1.mbarrier::arrive::one.shared::cluster.b64 [%0];"
                :: "r"(ctrl + 16 + (uint32_t)st * 8) : "memory");
        }
        if (i + 1 < nchunk) {
            if (i >= 1)   // buf (i+1)&1 was used by chunk i-1; wait for its MMAs
                mbar_wait(ctrl + 16 + (uint32_t)((i - 1) & 1) * 8,
                          (uint32_t)(((i - 1) >> 1) & 1));
            char* dst = smem + ((i + 1) & 1) * STAGE_BYTES_;
            const int kb = (i + 1) * 64;
            load_tile_bf16(a_hi, m0, kb, K, dst + 0 * TILE_BYTES_, t);
            load_tile_bf16(a_lo, m0, kb, K, dst + 1 * TILE_BYTES_, t);
            load_tile_bf16(b_hi, n0, kb, K, dst + 2 * TILE_BYTES_, t);
            load_tile_bf16(b_lo, n0, kb, K, dst + 3 * TILE_BYTES_, t);
            asm volatile("fence.proxy.async.shared::cta;" ::: "memory");
        }
        __syncthreads();
    }

    mbar_wait(ctrl + 16 + (uint32_t)((nchunk - 1) & 1) * 8,
              (uint32_t)(((nchunk - 1) >> 1) & 1));
    asm volatile("tcgen05.fence::after_thread_sync;" ::: "memory");

    // Epilogue: warp w -> rows (w&3)*32 + lane, column half (w>>2)*64
    const int mrow = m0 + (wid & 3) * 32 + lid;
    const int cb   = (wid >> 2) * 64;
#pragma unroll
    for (int half = 0; half < 2; half++) {
        uint32_t r[32];
        const uint32_t taddr = tmem + (uint32_t)(cb + half * 32);
        asm volatile(
            "tcgen05.ld.sync.aligned.32x32b.x32.b32 "
            "{%0, %1, %2, %3, %4, %5, %6, %7, "
            " %8, %9, %10, %11, %12, %13, %14, %15, "
            " %16, %17, %18, %19, %20, %21, %22, %23, "
            " %24, %25, %26, %27, %28, %29, %30, %31}, [%32];"
            : "=r"(r[0]),  "=r"(r[1]),  "=r"(r[2]),  "=r"(r[3]),
              "=r"(r[4]),  "=r"(r[5]),  "=r"(r[6]),  "=r"(r[7]),
              "=r"(r[8]),  "=r"(r[9]),  "=r"(r[10]), "=r"(r[11]),
              "=r"(r[12]), "=r"(r[13]), "=r"(r[14]), "=r"(r[15]),
              "=r"(r[16]), "=r"(r[17]), "=r"(r[18]), "=r"(r[19]),
              "=r"(r[20]), "=r"(r[21]), "=r"(r[22]), "=r"(r[23]),
              "=r"(r[24]), "=r"(r[25]), "=r"(r[26]), "=r"(r[27]),
              "=r"(r[28]), "=r"(r[29]), "=r"(r[30]), "=r"(r[31])
            : "r"(taddr));
        asm volatile("tcgen05.wait::ld.sync.aligned;" ::: "memory");
        float* cp = C + (size_t)mrow * ldc + n0 + cb + half * 32;
#pragma unroll
        for (int j = 0; j < 32; j += 4) {
            float4 v = make_float4(__uint_as_float(r[j]),     __uint_as_float(r[j + 1]),
                                   __uint_as_float(r[j + 2]), __uint_as_float(r[j + 3]));
            *(float4*)(cp + j) = v;
        }
    }

    __syncthreads();
    if (wid == 0) {
        asm volatile("tcgen05.relinquish_alloc_permit.cta_group::1.sync.aligned;" ::: "memory");
        asm volatile("tcgen05.dealloc.cta_group::1.sync.aligned.b32 %0, %1;"
                     :: "r"(tmem), "r"(128u));
    }
}

#else  // ------------------- FFMA fallback (non-'a' PTX pass) ----------------

__device__ __forceinline__ void ld4_split(
    const __nv_bfloat16* __restrict__ hi, const __nv_bfloat16* __restrict__ lo,
    size_t off, float* o)
{
    __nv_bfloat162 h0 = *(const __nv_bfloat162*)(hi + off);
    __nv_bfloat162 h1 = *(const __nv_bfloat162*)(hi + off + 2);
    __nv_bfloat162 l0 = *(const __nv_bfloat162*)(lo + off);
    __nv_bfloat162 l1 = *(const __nv_bfloat162*)(lo + off + 2);
    o[0] = __bfloat162float(h0.x) + __bfloat162float(l0.x);
    o[1] = __bfloat162float(h0.y) + __bfloat162float(l0.y);
    o[2] = __bfloat162float(h1.x) + __bfloat162float(l1.x);
    o[3] = __bfloat162float(h1.y) + __bfloat162float(l1.y);
}

__device__ __forceinline__ void gemm_body(
    const __nv_bfloat16* __restrict__ a_hi, const __nv_bfloat16* __restrict__ a_lo,
    const __nv_bfloat16* __restrict__ b_hi, const __nv_bfloat16* __restrict__ b_lo,
    float* __restrict__ C, int K, int ldc)
{
    __shared__ float As[8][132];
    __shared__ float Bs[8][132];

    const int t  = threadIdx.x;
    const int m0 = blockIdx.y * 128;
    const int n0 = blockIdx.x * 128;
    const int ty = t >> 4;
    const int tx = t & 15;
    const int lrow = t >> 1;
    const int lcol = (t & 1) << 2;

    float acc[8][8];
#pragma unroll
    for (int i = 0; i < 8; i++)
#pragma unroll
        for (int j = 0; j < 8; j++) acc[i][j] = 0.f;

    const size_t aoff = (size_t)(m0 + lrow) * K + lcol;
    const size_t boff = (size_t)(n0 + lrow) * K + lcol;

    float av[4], bv[4];
    ld4_split(a_hi, a_lo, aoff, av);
    ld4_split(b_hi, b_lo, boff, bv);

    for (int k0 = 0; k0 < K; k0 += 8) {
#pragma unroll
        for (int q = 0; q < 4; q++) {
            As[lcol + q][lrow] = av[q];
            Bs[lcol + q][lrow] = bv[q];
        }
        __syncthreads();

        if (k0 + 8 < K) {
            ld4_split(a_hi, a_lo, aoff + k0 + 8, av);
            ld4_split(b_hi, b_lo, boff + k0 + 8, bv);
        }

#pragma unroll
        for (int k = 0; k < 8; k++) {
            float ra[8], rb[8];
            *(float4*)&ra[0] = *(const float4*)&As[k][ty * 8];
            *(float4*)&ra[4] = *(const float4*)&As[k][ty * 8 + 4];
            *(float4*)&rb[0] = *(const float4*)&Bs[k][tx * 8];
            *(float4*)&rb[4] = *(const float4*)&Bs[k][tx * 8 + 4];
#pragma unroll
            for (int i = 0; i < 8; i++)
#pragma unroll
                for (int j = 0; j < 8; j++)
                    acc[i][j] = fmaf(ra[i], rb[j], acc[i][j]);
        }
        __syncthreads();
    }

#pragma unroll
    for (int i = 0; i < 8; i++) {
        const int m = m0 + ty * 8 + i;
#pragma unroll
        for (int j = 0; j < 8; j += 4) {
            const int n = n0 + tx * 8 + j;
            float4 v = make_float4(acc[i][j], acc[i][j + 1],
                                   acc[i][j + 2], acc[i][j + 3]);
            *(float4*)(C + (size_t)m * ldc + n) = v;
        }
    }
}
#endif  // TC_OK

__global__ void __launch_bounds__(256)
gemm_qkv_tc_kernel()
{
    gemm_body(g_h_hi, g_h_lo, g_wq_hi, g_wq_lo, g_qkv, HID_, QKV_PAD_);
}

__global__ void __launch_bounds__(256)
gemm_o_tc_kernel(float* __restrict__ out)
{
    gemm_body(g_at_hi, g_at_lo, g_wo_hi, g_wo_lo, out, ADIM_, HID_);
}

// ---------------------------------------------------------------------------
// RoPE in place on g_qkv: q heads (16) and k heads (8), 64 pairs each
// ---------------------------------------------------------------------------
__global__ void __launch_bounds__(256)
rope_kernel(const float* __restrict__ cosp, const float* __restrict__ sinp)
{
    const int row = blockIdx.x;            // 0..4095 (= b*S + s)
    const int s   = row & (S_ - 1);
    float* rp = g_qkv + (size_t)row * QKV_PAD_;

    for (int idx = threadIdx.x; idx < (NH_ + NKV_) * (HD_ / 2); idx += 256) {
        const int head = idx >> 6;          // 0..23
        const int d    = idx & 63;          // 0..63
        const int off  = (head < NH_) ? head * HD_
                                      : OFF_K_ + (head - NH_) * HD_;
        const float x1 = rp[off + d];
        const float x2 = rp[off + d + 64];
        const float c1 = cosp[s * HD_ + d];
        const float c2 = cosp[s * HD_ + d + 64];
        const float s1 = sinp[s * HD_ + d];
        const float s2 = sinp[s * HD_ + d + 64];
        rp[off + d]      = x1 * c1 - x2 * s1;
        rp[off + d + 64] = x2 * c2 + x1 * s2;
    }
}

// ---------------------------------------------------------------------------
// Flash-style attention, fp32; epilogue emits bf16 hi/lo for the O projection
// ---------------------------------------------------------------------------
constexpr int ATTN_SMEM_ = (128 * 65 + 128 * 65 + 64 * 128 + 64 * 65) * 4; // 115968

__global__ void __launch_bounds__(256)
attn_kernel()
{
    extern __shared__ float sm[];
    float* Qs = sm;                 // 128*65
    float* Ks = Qs + 128 * 65;      // 128*65
    float* Vs = Ks + 128 * 65;      // 64*128
    float* Ps = Vs + 64 * 128;      // 64*65

    const int qt = blockIdx.x;      // 0..31
    const int h  = blockIdx.y;      // 0..15
    const int b  = blockIdx.z;      // 0..1
    const int kh = h >> 1;          // GQA: rep = 2
    const int t  = threadIdx.x;
    const int ty = t >> 4;
    const int tx = t & 15;
    const int q0 = qt * 64;

    const float* qbase = g_qkv + (size_t)b * S_ * QKV_PAD_;

    {
        const float sc = 0.08838834764831845f;   // 1/sqrt(128)
#pragma unroll
        for (int it = 0; it < 8; it++) {
            const int lin = t + 256 * it;
            const int r   = lin >> 5;
            const int d0  = (lin & 31) << 2;
            const float4 v = *(const float4*)(
                qbase + (size_t)(q0 + r) * QKV_PAD_ + h * HD_ + d0);
            Qs[(d0 + 0) * 65 + r] = v.x * sc;
            Qs[(d0 + 1) * 65 + r] = v.y * sc;
            Qs[(d0 + 2) * 65 + r] = v.z * sc;
            Qs[(d0 + 3) * 65 + r] = v.w * sc;
        }
    }

    float m_i[4], l_i[4], acc[4][8];
#pragma unroll
    for (int i = 0; i < 4; i++) {
        m_i[i] = -1e30f;
        l_i[i] = 0.f;
#pragma unroll
        for (int j = 0; j < 8; j++) acc[i][j] = 0.f;
    }
    __syncthreads();

    const int koff = OFF_K_ + kh * HD_;
    const int voff = OFF_V_ + kh * HD_;

    for (int kt = 0; kt < S_ / 64; kt++) {
        const int k0 = kt * 64;

#pragma unroll
        for (int it = 0; it < 8; it++) {
            const int lin = t + 256 * it;
            const int r   = lin >> 5;
            const int d0  = (lin & 31) << 2;
            const float* rowp = qbase + (size_t)(k0 + r) * QKV_PAD_;
            const float4 kv = *(const float4*)(rowp + koff + d0);
            Ks[(d0 + 0) * 65 + r] = kv.x;
            Ks[(d0 + 1) * 65 + r] = kv.y;
            Ks[(d0 + 2) * 65 + r] = kv.z;
            Ks[(d0 + 3) * 65 + r] = kv.w;
            *(float4*)(Vs + r * 128 + d0) = *(const float4*)(rowp + voff + d0);
        }
        __syncthreads();

        float s4[4][4];
#pragma unroll
        for (int i = 0; i < 4; i++)
#pragma unroll
            for (int j = 0; j < 4; j++) s4[i][j] = 0.f;

#pragma unroll 8
        for (int k = 0; k < 128; k++) {
            float a0 = Qs[k * 65 + ty * 4 + 0];
            float a1 = Qs[k * 65 + ty * 4 + 1];
            float a2 = Qs[k * 65 + ty * 4 + 2];
            float a3 = Qs[k * 65 + ty * 4 + 3];
            float b0 = Ks[k * 65 + tx * 4 + 0];
            float b1 = Ks[k * 65 + tx * 4 + 1];
            float b2 = Ks[k * 65 + tx * 4 + 2];
            float b3 = Ks[k * 65 + tx * 4 + 3];
            s4[0][0] = fmaf(a0, b0, s4[0][0]); s4[0][1] = fmaf(a0, b1, s4[0][1]);
            s4[0][2] = fmaf(a0, b2, s4[0][2]); s4[0][3] = fmaf(a0, b3, s4[0][3]);
            s4[1][0] = fmaf(a1, b0, s4[1][0]); s4[1][1] = fmaf(a1, b1, s4[1][1]);
            s4[1][2] = fmaf(a1, b2, s4[1][2]); s4[1][3] = fmaf(a1, b3, s4[1][3]);
            s4[2][0] = fmaf(a2, b0, s4[2][0]); s4[2][1] = fmaf(a2, b1, s4[2][1]);
            s4[2][2] = fmaf(a2, b2, s4[2][2]); s4[2][3] = fmaf(a2, b3, s4[2][3]);
            s4[3][0] = fmaf(a3, b0, s4[3][0]); s4[3][1] = fmaf(a3, b1, s4[3][1]);
            s4[3][2] = fmaf(a3, b2, s4[3][2]); s4[3][3] = fmaf(a3, b3, s4[3][3]);
        }

#pragma unroll
        for (int i = 0; i < 4; i++) {
            float rm = fmaxf(fmaxf(s4[i][0], s4[i][1]), fmaxf(s4[i][2], s4[i][3]));
#pragma unroll
            for (int o = 1; o < 16; o <<= 1)
                rm = fmaxf(rm, __shfl_xor_sync(0xffffffffu, rm, o));
            const float mn = fmaxf(m_i[i], rm);
            const float al = __expf(m_i[i] - mn);
            m_i[i] = mn;
            float rs = 0.f;
#pragma unroll
            for (int j = 0; j < 4; j++) {
                const float p = __expf(s4[i][j] - mn);
                rs += p;
                Ps[(tx * 4 + j) * 65 + ty * 4 + i] = p;
            }
#pragma unroll
            for (int o = 1; o < 16; o <<= 1)
                rs += __shfl_xor_sync(0xffffffffu, rs, o);
            l_i[i] = l_i[i] * al + rs;
#pragma unroll
            for (int j = 0; j < 8; j++) acc[i][j] *= al;
        }
        __syncthreads();

#pragma unroll 4
        for (int c = 0; c < 64; c++) {
            const float a0 = Ps[c * 65 + ty * 4 + 0];
            const float a1 = Ps[c * 65 + ty * 4 + 1];
            const float a2 = Ps[c * 65 + ty * 4 + 2];
            const float a3 = Ps[c * 65 + ty * 4 + 3];
            float rb[8];
            *(float4*)&rb[0] = *(const float4*)(Vs + c * 128 + tx * 8);
            *(float4*)&rb[4] = *(const float4*)(Vs + c * 128 + tx * 8 + 4);
#pragma unroll
            for (int j = 0; j < 8; j++) {
                acc[0][j] = fmaf(a0, rb[j], acc[0][j]);
                acc[1][j] = fmaf(a1, rb[j], acc[1][j]);
                acc[2][j] = fmaf(a2, rb[j], acc[2][j]);
                acc[3][j] = fmaf(a3, rb[j], acc[3][j]);
            }
        }
        __syncthreads();
    }

    // Epilogue: gate * O/l, then split to bf16 hi/lo for the O-projection
#pragma unroll
    for (int i = 0; i < 4; i++) {
        const int r = q0 + ty * 4 + i;
        const float gl = qbase[(size_t)r * QKV_PAD_ + OFF_GATE_ + h];
        const float gate = 1.f / (1.f + __expf(-gl));
        const float w = gate / l_i[i];
        const size_t e = (size_t)(b * S_ + r) * ADIM_ + h * HD_ + tx * 8;
        float o[8];
#pragma unroll
        for (int j = 0; j < 8; j++) o[j] = acc[i][j] * w;
#pragma unroll
        for (int j = 0; j < 8; j += 2) {
            __nv_bfloat16 h0 = __float2bfloat16_rn(o[j]);
            __nv_bfloat16 h1 = __float2bfloat16_rn(o[j + 1]);
            __nv_bfloat16 l0 = __float2bfloat16_rn(o[j]     - __bfloat162float(h0));
            __nv_bfloat16 l1 = __float2bfloat16_rn(o[j + 1] - __bfloat162float(h1));
            __nv_bfloat162 hp; hp.x = h0; hp.y = h1;
            __nv_bfloat162 lp; lp.x = l0; lp.y = l1;
            *(__nv_bfloat162*)(g_at_hi + e + j) = hp;
            *(__nv_bfloat162*)(g_at_lo + e + j) = lp;
        }
    }
}

// ---------------------------------------------------------------------------
// Launch
// ---------------------------------------------------------------------------
extern "C" void kernel_launch(void* const* d_in, const int* in_sizes, int n_in,
                              void* d_out, int out_size)
{
    (void)in_sizes; (void)n_in; (void)out_size;
    const float* hidden = (const float*)d_in[0];   // [B,S,HID]
    const float* cosp   = (const float*)d_in[1];   // [S,HD]
    const float* sinp   = (const float*)d_in[2];   // [S,HD]
    const float* w_qkv  = (const float*)d_in[3];   // [QKV_OUT,HID]
    const float* w_o    = (const float*)d_in[4];   // [HID, NH*HD]
    float* out = (float*)d_out;                    // [B,S,HID]

    cudaFuncSetAttribute(gemm_qkv_tc_kernel,
                         cudaFuncAttributeMaxDynamicSharedMemorySize, GEMM_SMEM_);
    cudaFuncSetAttribute(gemm_o_tc_kernel,
                         cudaFuncAttributeMaxDynamicSharedMemorySize, GEMM_SMEM_);
    cudaFuncSetAttribute(attn_kernel,
                         cudaFuncAttributeMaxDynamicSharedMemorySize, ATTN_SMEM_);

    // 0) split fp32 -> bf16 hi/lo (weights + activations)
    split_hidden_kernel<<<8192, 256>>>(hidden);
    split_wq_kernel<<<8448, 256>>>(w_qkv);
    split_wo_kernel<<<4096, 256>>>(w_o);

    // 1) QKV projection: g_qkv = hidden @ w_qkv^T
    gemm_qkv_tc_kernel<<<dim3(QKV_PAD_ / 128, MROWS_ / 128), 256, GEMM_SMEM_>>>();

    // 2) RoPE in place on q and k
    rope_kernel<<<MROWS_, 256>>>(cosp, sinp);

    // 3) Attention + gate -> g_at_hi/lo (bf16 split)
    attn_kernel<<<dim3(S_ / 64, NH_, B_), 256, ATTN_SMEM_>>>();

    // 4) Output projection: out = attn @ w_o^T
    gemm_o_tc_kernel<<<dim3(HID_ / 128, MROWS_ / 128), 256, GEMM_SMEM_>>>(out);
}